// round 7
// baseline (speedup 1.0000x reference)
#include <cuda_runtime.h>
#include <math.h>

// GaussianConditionalStanh: y = inputs - means; symbol = searchsorted(mid, y)
// (nearest level in sorted 60-entry codebook, 'left'); dequant = codebook[sym] + means.
// Output layout: [symbols as float (N) | dequant (N)], N = 16*192*96*96.
//
// Near-linear codebook -> arithmetic guess g = round((y-c0)*inv_step), then a
// 4-wide probe window [g-2, g+1] fetched as ONE float4 from a precomposed
// table pmv[g] = (mid[g-2], mid[g-1], mid[g], mid[g+1]) (+-inf padded).
// idx = g-2 + #(probe < y)  (exactness over +-2 window validated, rel_err==0).

#define NLEV 60
#define NMID 59
#define WOFF 4  // staging-array front padding

__global__ void __launch_bounds__(256, 8)
stanh_quant_kernel(const float4* __restrict__ x,
                   const float4* __restrict__ mu,
                   const float* __restrict__ cb,
                   float4* __restrict__ sym_out,
                   float4* __restrict__ deq_out,
                   int n4) {
    __shared__ float mstage[WOFF + NMID + 5];  // 68: [-inf x4 | mids x59 | +inf x5]
    __shared__ float4 pmv[NLEV];               // pmv[g] = mids[g-2 .. g+1]
    __shared__ float scb[NLEV];
    __shared__ float sconst[2];                // inv_step, bias

    int t = threadIdx.x;
    if (t < WOFF + NMID + 5) {
        float v;
        if (t < WOFF)             v = -__int_as_float(0x7f800000);
        else if (t < WOFF + NMID) v = 0.5f * (cb[t - WOFF] + cb[t - WOFF + 1]);
        else                      v = __int_as_float(0x7f800000);
        mstage[t] = v;
    }
    if (t < NLEV) scb[t] = cb[t];
    if (t == 0) {
        float c0 = cb[0], cL = cb[NLEV - 1];
        float inv_step = (float)(NLEV - 1) / (cL - c0);
        sconst[0] = inv_step;
        sconst[1] = -c0 * inv_step;
    }
    __syncthreads();
    if (t < NLEV) {
        // mids[g-2..g+1] = mstage[g+WOFF-2 .. g+WOFF+1]
        pmv[t] = make_float4(mstage[t + WOFF - 2], mstage[t + WOFF - 1],
                             mstage[t + WOFF + 0], mstage[t + WOFF + 1]);
    }
    __syncthreads();

    float inv_step = sconst[0];
    float bias     = sconst[1];

    // 2 float4 per thread, strided within the block for coalescing.
    int i0 = blockIdx.x * (blockDim.x * 2) + t;
    int i1 = i0 + blockDim.x;
    bool p1 = (i1 < n4);
    if (i0 >= n4) return;

    // Batch all global loads first (MLP).
    float4 xv0 = __ldcs(&x[i0]);
    float4 mv0 = __ldcs(&mu[i0]);
    float4 xv1, mv1;
    if (p1) { xv1 = __ldcs(&x[i1]); mv1 = __ldcs(&mu[i1]); }

    #define QUANT1(xi, mi, so, do)                                   \
    {                                                                \
        float y = (xi) - (mi);                                       \
        int g = __float2int_rn(fmaf(y, inv_step, bias));             \
        g = min(max(g, 0), NLEV - 1);                                \
        float4 pv = pmv[g];                                          \
        int c = (pv.x < y) + (pv.y < y) + (pv.z < y) + (pv.w < y);   \
        int idx = g - 2 + c;                                         \
        idx = min(max(idx, 0), NLEV - 1);                            \
        (so) = (float)idx;                                           \
        (do) = scb[idx] + (mi);                                      \
    }

    float4 s0, d0;
    QUANT1(xv0.x, mv0.x, s0.x, d0.x);
    QUANT1(xv0.y, mv0.y, s0.y, d0.y);
    QUANT1(xv0.z, mv0.z, s0.z, d0.z);
    QUANT1(xv0.w, mv0.w, s0.w, d0.w);
    __stcs(&sym_out[i0], s0);
    __stcs(&deq_out[i0], d0);

    if (p1) {
        float4 s1, d1;
        QUANT1(xv1.x, mv1.x, s1.x, d1.x);
        QUANT1(xv1.y, mv1.y, s1.y, d1.y);
        QUANT1(xv1.z, mv1.z, s1.z, d1.z);
        QUANT1(xv1.w, mv1.w, s1.w, d1.w);
        __stcs(&sym_out[i1], s1);
        __stcs(&deq_out[i1], d1);
    }
    #undef QUANT1
}

extern "C" void kernel_launch(void* const* d_in, const int* in_sizes, int n_in,
                              void* d_out, int out_size) {
    const float* x  = (const float*)d_in[0];   // inputs  [B,C,H,W] f32
    const float* mu = (const float*)d_in[1];   // means   [B,C,H,W] f32
    const float* cb = (const float*)d_in[2];   // codebook [60] f32

    int n  = in_sizes[0];          // 28,311,552 (divisible by 8)
    int n4 = n >> 2;

    float* out = (float*)d_out;
    float* sym = out;              // first N: symbols (as float)
    float* deq = out + n;          // next N: dequant

    int threads = 256;
    int per_block = threads * 2;   // 2 float4 per thread
    int blocks = (n4 + per_block - 1) / per_block;
    stanh_quant_kernel<<<blocks, threads>>>(
        (const float4*)x, (const float4*)mu, cb,
        (float4*)sym, (float4*)deq, n4);
}

// round 11
// speedup vs baseline: 1.0018x; 1.0018x over previous
#include <cuda_runtime.h>
#include <math.h>

// GaussianConditionalStanh: y = inputs - means; symbol = searchsorted(mid, y)
// (nearest level in sorted 60-entry codebook, 'left'); dequant = codebook[sym] + means.
// Output layout: [symbols as float (N) | dequant (N)], N = 16*192*96*96.
//
// Near-linear codebook -> arithmetic guess g = round((y-c0)*inv_step) + a
// 4-wide SCALAR probe window [g-2, g+1] over +-inf padded midpoints.
// idx = g-2 + #(mid < y). (Scalar probes beat a float4 table: divergent
// LDS.128 costs >=4 crossbar phases + conflicts — measured R6.)

#define NLEV 60
#define NMID 59
#define WOFF 4  // padding in front of midpoint array

__global__ void __launch_bounds__(256, 6)
stanh_quant_kernel(const float4* __restrict__ x,
                   const float4* __restrict__ mu,
                   const float* __restrict__ cb,
                   float4* __restrict__ sym_out,
                   float4* __restrict__ deq_out,
                   int n4) {
    __shared__ float pm[WOFF + NMID + 5];  // 68: [-inf x4 | mids x59 | +inf x5]
    __shared__ float scb[NLEV];
    __shared__ float sconst[2];            // inv_step, bias

    int t = threadIdx.x;
    if (t < WOFF + NMID + 5) {
        float v;
        if (t < WOFF)             v = -__int_as_float(0x7f800000);
        else if (t < WOFF + NMID) v = 0.5f * (cb[t - WOFF] + cb[t - WOFF + 1]);
        else                      v = __int_as_float(0x7f800000);
        pm[t] = v;
    }
    if (t < NLEV) scb[t] = cb[t];
    if (t == 0) {
        float c0 = cb[0], cL = cb[NLEV - 1];
        float inv_step = (float)(NLEV - 1) / (cL - c0);
        sconst[0] = inv_step;
        sconst[1] = -c0 * inv_step;
    }
    __syncthreads();

    float inv_step = sconst[0];
    float bias     = sconst[1];

    #define QUANT1(xi, mi, so, dq)                          \
    {                                                       \
        float y = (xi) - (mi);                              \
        int g = __float2int_rn(fmaf(y, inv_step, bias));    \
        g = min(max(g, 0), NLEV - 1);                       \
        int c = 0;                                          \
        c += pm[g + WOFF - 2] < y;                          \
        c += pm[g + WOFF - 1] < y;                          \
        c += pm[g + WOFF + 0] < y;                          \
        c += pm[g + WOFF + 1] < y;                          \
        int idx = g - 2 + c;                                \
        idx = min(max(idx, 0), NLEV - 1);                   \
        (so) = (float)idx;                                  \
        (dq) = scb[idx] + (mi);                             \
    }

    #define DO_PAIR(ia, ib)                                  \
    {                                                        \
        float4 xa = __ldcs(&x[ia]);                          \
        float4 ma = __ldcs(&mu[ia]);                         \
        float4 xb = __ldcs(&x[ib]);                          \
        float4 mb = __ldcs(&mu[ib]);                         \
        float4 sa, da, sb, db;                               \
        QUANT1(xa.x, ma.x, sa.x, da.x);                      \
        QUANT1(xa.y, ma.y, sa.y, da.y);                      \
        QUANT1(xa.z, ma.z, sa.z, da.z);                      \
        QUANT1(xa.w, ma.w, sa.w, da.w);                      \
        QUANT1(xb.x, mb.x, sb.x, db.x);                      \
        QUANT1(xb.y, mb.y, sb.y, db.y);                      \
        QUANT1(xb.z, mb.z, sb.z, db.z);                      \
        QUANT1(xb.w, mb.w, sb.w, db.w);                      \
        __stcs(&sym_out[ia], sa);                            \
        __stcs(&deq_out[ia], da);                            \
        __stcs(&sym_out[ib], sb);                            \
        __stcs(&deq_out[ib], db);                            \
    }

    // 4 float4 per thread, block-strided for coalescing.
    int base = blockIdx.x * (blockDim.x * 4) + t;
    int i0 = base;
    int i1 = base + blockDim.x;
    int i2 = base + blockDim.x * 2;
    int i3 = base + blockDim.x * 3;

    if (i3 < n4) {
        DO_PAIR(i0, i1);
        DO_PAIR(i2, i3);
    } else {
        // Tail path (only last block)
        #define DO_ONE(ia)                                   \
        if ((ia) < n4) {                                     \
            float4 xa = __ldcs(&x[ia]);                      \
            float4 ma = __ldcs(&mu[ia]);                     \
            float4 sa, da;                                   \
            QUANT1(xa.x, ma.x, sa.x, da.x);                  \
            QUANT1(xa.y, ma.y, sa.y, da.y);                  \
            QUANT1(xa.z, ma.z, sa.z, da.z);                  \
            QUANT1(xa.w, ma.w, sa.w, da.w);                  \
            __stcs(&sym_out[ia], sa);                        \
            __stcs(&deq_out[ia], da);                        \
        }
        DO_ONE(i0); DO_ONE(i1); DO_ONE(i2); DO_ONE(i3);
        #undef DO_ONE
    }
    #undef DO_PAIR
    #undef QUANT1
}

extern "C" void kernel_launch(void* const* d_in, const int* in_sizes, int n_in,
                              void* d_out, int out_size) {
    const float* x  = (const float*)d_in[0];   // inputs  [B,C,H,W] f32
    const float* mu = (const float*)d_in[1];   // means   [B,C,H,W] f32
    const float* cb = (const float*)d_in[2];   // codebook [60] f32

    int n  = in_sizes[0];          // 28,311,552 (divisible by 16)
    int n4 = n >> 2;

    float* out = (float*)d_out;
    float* sym = out;              // first N: symbols (as float)
    float* deq = out + n;          // next N: dequant

    int threads = 256;
    int per_block = threads * 4;   // 4 float4 per thread
    int blocks = (n4 + per_block - 1) / per_block;
    stanh_quant_kernel<<<blocks, threads>>>(
        (const float4*)x, (const float4*)mu, cb,
        (float4*)sym, (float4*)deq, n4);
}